// round 1
// baseline (speedup 1.0000x reference)
#include <cuda_runtime.h>
#include <cstdint>

#define N_NODES 10000
#define WPR 313              // ceil(10000/32) words per bitmask row
#define D 256
#define E_EDGES 320000
#define CHUNK_WORDS 64
#define BUF 2048             // CHUNK_WORDS*32 bits max per chunk

// Scratch (no allocs allowed): 12.52 MB bitmask + dinv + h
__device__ uint32_t g_bits[N_NODES * WPR];
__device__ float    g_dinv[N_NODES];
__device__ float    g_h[N_NODES * D];
__device__ int      g_odd;   // nonzero => edge_index is int32

// ---------------------------------------------------------------------------
// Detect edge_index dtype: if int64, every odd 32-bit word (high half of
// values < 10000) among the first 2*E words is zero.
__global__ void detect_kernel(const int* __restrict__ ei) {
    unsigned v = 0;
    int stride = 2 * gridDim.x * blockDim.x;
    for (int i = 2 * (blockIdx.x * blockDim.x + threadIdx.x) + 1; i < 2 * E_EDGES; i += stride)
        v |= (unsigned)ei[i];
    #pragma unroll
    for (int o = 16; o; o >>= 1) v |= __shfl_xor_sync(0xffffffffu, v, o);
    if ((threadIdx.x & 31) == 0 && v) atomicOr(&g_odd, 1);
}

// ---------------------------------------------------------------------------
// Set adjacency bits (symmetric, OR = idempotent dedup, order-independent)
__global__ void set_bits_kernel(const int* __restrict__ ei32) {
    int e = blockIdx.x * blockDim.x + threadIdx.x;
    if (e >= E_EDGES) return;
    int src, dst;
    if (g_odd == 0) {  // int64 layout
        const long long* ei = (const long long*)ei32;
        src = (int)ei[e];
        dst = (int)ei[E_EDGES + e];
    } else {
        src = ei32[e];
        dst = ei32[E_EDGES + e];
    }
    atomicOr(&g_bits[src * WPR + (dst >> 5)], 1u << (dst & 31));
    atomicOr(&g_bits[dst * WPR + (src >> 5)], 1u << (src & 31));
}

// ---------------------------------------------------------------------------
// dinv[i] = rsqrt(popcount(row i) + 1)   (+1 from the added identity)
__global__ void deg_kernel() {
    int row = blockIdx.x * 8 + (threadIdx.x >> 5);
    if (row >= N_NODES) return;
    int lane = threadIdx.x & 31;
    const uint32_t* w = &g_bits[row * WPR];
    unsigned cnt = 0;
    for (int i = lane; i < WPR; i += 32) cnt += __popc(w[i]);
    #pragma unroll
    for (int o = 16; o; o >>= 1) cnt += __shfl_down_sync(0xffffffffu, cnt, o);
    if (lane == 0) g_dinv[row] = rsqrtf((float)cnt + 1.0f);
}

// ---------------------------------------------------------------------------
// h = (x @ W) scaled by dinv[row] in the epilogue.
// BM=64, BN=64, BK=32, 256 threads (16x16), 4x4 microtile.
__global__ void gemm_kernel(const float* __restrict__ x, const float* __restrict__ w) {
    __shared__ float xs[64][33];
    __shared__ float ws[32][65];
    int tx = threadIdx.x & 15, ty = threadIdx.x >> 4;
    int m0 = blockIdx.x * 64, n0 = blockIdx.y * 64;
    float acc[4][4] = {};
    for (int k0 = 0; k0 < D; k0 += 32) {
        #pragma unroll
        for (int i = threadIdx.x; i < 64 * 32; i += 256) {
            int r = i >> 5, c = i & 31;
            int gr = m0 + r;
            xs[r][c] = (gr < N_NODES) ? x[gr * D + k0 + c] : 0.0f;
        }
        #pragma unroll
        for (int i = threadIdx.x; i < 32 * 64; i += 256) {
            int r = i >> 6, c = i & 63;
            ws[r][c] = w[(k0 + r) * D + n0 + c];
        }
        __syncthreads();
        #pragma unroll
        for (int k = 0; k < 32; k++) {
            float a[4], b[4];
            #pragma unroll
            for (int i = 0; i < 4; i++) a[i] = xs[ty * 4 + i][k];
            #pragma unroll
            for (int j = 0; j < 4; j++) b[j] = ws[k][tx * 4 + j];
            #pragma unroll
            for (int i = 0; i < 4; i++)
                #pragma unroll
                for (int j = 0; j < 4; j++)
                    acc[i][j] += a[i] * b[j];
        }
        __syncthreads();
    }
    #pragma unroll
    for (int i = 0; i < 4; i++) {
        int gr = m0 + ty * 4 + i;
        if (gr < N_NODES) {
            float dv = g_dinv[gr];
            #pragma unroll
            for (int j = 0; j < 4; j++)
                g_h[gr * D + n0 + tx * 4 + j] = acc[i][j] * dv;
        }
    }
}

// ---------------------------------------------------------------------------
// out[i,:] = dinv[i] * ( sum_{j: bit(i,j)} h[j,:] + h[i,:] )
// (h already prescaled by dinv[j]; the +h[i,:] term is the identity self-loop)
// Block per row, 256 threads = one output dim each.
// Deterministic extraction: prefix-sum of per-word popcounts (no atomics).
__global__ void agg_kernel(float* __restrict__ out) {
    __shared__ int s_idx[BUF];
    __shared__ int s_pc[CHUNK_WORDS + 1];
    int row = blockIdx.x;
    int d = threadIdx.x;
    const uint32_t* wrow = &g_bits[row * WPR];
    float acc = 0.0f;

    for (int w0 = 0; w0 < WPR; w0 += CHUNK_WORDS) {
        // per-word popcounts
        uint32_t myw = 0;
        if (d < CHUNK_WORDS) {
            int wi = w0 + d;
            myw = (wi < WPR) ? wrow[wi] : 0u;
            s_pc[d] = __popc(myw);
        }
        __syncthreads();
        // extract set bits at deterministic positions
        int cnt_total = 0;
        if (d < CHUNK_WORDS) {
            int pos = 0;
            #pragma unroll 8
            for (int t = 0; t < CHUNK_WORDS; t++) {
                int p = s_pc[t];
                if (t < d) pos += p;
                cnt_total += p;  // every extracting thread computes total
            }
            uint32_t w = myw;
            int base = (w0 + d) * 32;
            while (w) {
                int b = __ffs(w) - 1;
                w &= w - 1;
                s_idx[pos++] = base + b;
            }
            if (d == 0) s_pc[CHUNK_WORDS] = cnt_total;
        }
        __syncthreads();
        int cnt = s_pc[CHUNK_WORDS];
        #pragma unroll 4
        for (int k = 0; k < cnt; k++) {
            acc += g_h[s_idx[k] * D + d];
        }
        __syncthreads();
    }
    float di = g_dinv[row];
    out[row * D + d] = di * (acc + g_h[row * D + d]);
}

// ---------------------------------------------------------------------------
extern "C" void kernel_launch(void* const* d_in, const int* in_sizes, int n_in,
                              void* d_out, int out_size) {
    const float* x  = (const float*)d_in[0];
    const int*   ei = (const int*)d_in[1];
    const float* w  = (const float*)d_in[2];
    float* out = (float*)d_out;

    void* bits_ptr = nullptr;
    void* odd_ptr = nullptr;
    cudaGetSymbolAddress(&bits_ptr, g_bits);
    cudaGetSymbolAddress(&odd_ptr, g_odd);
    cudaMemsetAsync(bits_ptr, 0, sizeof(uint32_t) * (size_t)N_NODES * WPR);
    cudaMemsetAsync(odd_ptr, 0, sizeof(int));

    detect_kernel<<<256, 256>>>(ei);
    set_bits_kernel<<<(E_EDGES + 255) / 256, 256>>>(ei);
    deg_kernel<<<(N_NODES + 7) / 8, 256>>>();
    gemm_kernel<<<dim3((N_NODES + 63) / 64, D / 64), 256>>>(x, w);
    agg_kernel<<<N_NODES, 256>>>(out);
}

// round 2
// speedup vs baseline: 1.4728x; 1.4728x over previous
#include <cuda_runtime.h>
#include <cuda_fp16.h>
#include <cstdint>

#define N_NODES 10000
#define WPR 313              // ceil(10000/32) words per bitmask row
#define D 256
#define E_EDGES 320000
#define CHUNK_WORDS 64
#define BUF 2048             // CHUNK_WORDS*32 bits max per chunk

// Scratch (no allocs allowed): 12.52 MB bitmask + dinv + h (fp16)
__device__ uint32_t g_bits[N_NODES * WPR];
__device__ float    g_dinv[N_NODES];
__device__ __half2  g_hh[N_NODES * (D / 2)];   // h prescaled by dinv[row], fp16
__device__ int      g_odd;   // nonzero => edge_index is int32

// ---------------------------------------------------------------------------
// Detect edge_index dtype: if int64, every odd 32-bit word (high half of
// values < 10000) among the first 2*E words is zero.
__global__ void detect_kernel(const int* __restrict__ ei) {
    unsigned v = 0;
    int stride = 2 * gridDim.x * blockDim.x;
    for (int i = 2 * (blockIdx.x * blockDim.x + threadIdx.x) + 1; i < 2 * E_EDGES; i += stride)
        v |= (unsigned)ei[i];
    #pragma unroll
    for (int o = 16; o; o >>= 1) v |= __shfl_xor_sync(0xffffffffu, v, o);
    if ((threadIdx.x & 31) == 0 && v) atomicOr(&g_odd, 1);
}

// ---------------------------------------------------------------------------
// Set adjacency bits (symmetric, OR = idempotent dedup, order-independent)
__global__ void set_bits_kernel(const int* __restrict__ ei32) {
    int e = blockIdx.x * blockDim.x + threadIdx.x;
    if (e >= E_EDGES) return;
    int src, dst;
    if (g_odd == 0) {  // int64 layout
        const long long* ei = (const long long*)ei32;
        src = (int)ei[e];
        dst = (int)ei[E_EDGES + e];
    } else {
        src = ei32[e];
        dst = ei32[E_EDGES + e];
    }
    atomicOr(&g_bits[src * WPR + (dst >> 5)], 1u << (dst & 31));
    atomicOr(&g_bits[dst * WPR + (src >> 5)], 1u << (src & 31));
}

// ---------------------------------------------------------------------------
// dinv[i] = rsqrt(popcount(row i) + 1)   (+1 from the added identity)
__global__ void deg_kernel() {
    int row = blockIdx.x * 8 + (threadIdx.x >> 5);
    if (row >= N_NODES) return;
    int lane = threadIdx.x & 31;
    const uint32_t* w = &g_bits[row * WPR];
    unsigned cnt = 0;
    for (int i = lane; i < WPR; i += 32) cnt += __popc(w[i]);
    #pragma unroll
    for (int o = 16; o; o >>= 1) cnt += __shfl_down_sync(0xffffffffu, cnt, o);
    if (lane == 0) g_dinv[row] = rsqrtf((float)cnt + 1.0f);
}

// ---------------------------------------------------------------------------
// h = (x @ W) * dinv[row], stored as fp16 pairs.
// BM=64, BN=64, BK=16, 128 threads, 8x4 microtile, register prefetch.
#define BM 64
#define BN 64
#define BK 16

__global__ void gemm_kernel(const float* __restrict__ x, const float* __restrict__ w) {
    __shared__ float As[BK][BM + 4];   // transposed: As[k][m]
    __shared__ float Bs[BK][BN];       // Bs[k][n]
    int t = threadIdx.x;
    int tx = t & 15;        // 16 col-groups of 4
    int ty = t >> 4;        // 8 row-groups of 8
    int m0 = blockIdx.x * BM, n0 = blockIdx.y * BN;

    // A tile: 64 rows x 16 k = 256 float4 (row = f>>2, c4 = (f&3)*4); 2 per thread
    // B tile: 16 rows x 64 n = 256 float4 (row = f>>4, c4 = (f&15)*4); 2 per thread
    int a_r0 = t >> 2,          a_c0 = (t & 3) * 4;
    int a_r1 = (t + 128) >> 2,  a_c1 = (t & 3) * 4;   // (t+128)&3 == t&3
    int b_r0 = t >> 4,          b_c0 = (t & 15) * 4;
    int b_r1 = (t + 128) >> 4,  b_c1 = (t & 15) * 4;

    float acc[8][4] = {};
    float4 pa0, pa1, pb0, pb1;

    // ---- load first k-tile into regs
    {
        int gm0 = m0 + a_r0, gm1 = m0 + a_r1;
        pa0 = (gm0 < N_NODES) ? *(const float4*)&x[gm0 * D + a_c0] : make_float4(0,0,0,0);
        pa1 = (gm1 < N_NODES) ? *(const float4*)&x[gm1 * D + a_c1] : make_float4(0,0,0,0);
        pb0 = *(const float4*)&w[b_r0 * D + n0 + b_c0];
        pb1 = *(const float4*)&w[b_r1 * D + n0 + b_c1];
    }

    for (int k0 = 0; k0 < D; k0 += BK) {
        // ---- store prefetched regs to smem
        As[a_c0 + 0][a_r0] = pa0.x; As[a_c0 + 1][a_r0] = pa0.y;
        As[a_c0 + 2][a_r0] = pa0.z; As[a_c0 + 3][a_r0] = pa0.w;
        As[a_c1 + 0][a_r1] = pa1.x; As[a_c1 + 1][a_r1] = pa1.y;
        As[a_c1 + 2][a_r1] = pa1.z; As[a_c1 + 3][a_r1] = pa1.w;
        *(float4*)&Bs[b_r0][b_c0] = pb0;
        *(float4*)&Bs[b_r1][b_c1] = pb1;
        __syncthreads();

        // ---- prefetch next k-tile
        int kn = k0 + BK;
        if (kn < D) {
            int gm0 = m0 + a_r0, gm1 = m0 + a_r1;
            pa0 = (gm0 < N_NODES) ? *(const float4*)&x[gm0 * D + kn + a_c0] : make_float4(0,0,0,0);
            pa1 = (gm1 < N_NODES) ? *(const float4*)&x[gm1 * D + kn + a_c1] : make_float4(0,0,0,0);
            pb0 = *(const float4*)&w[(kn + b_r0) * D + n0 + b_c0];
            pb1 = *(const float4*)&w[(kn + b_r1) * D + n0 + b_c1];
        }

        // ---- compute current tile
        #pragma unroll
        for (int k = 0; k < BK; k++) {
            float a[8], b[4];
            *(float4*)&a[0] = *(float4*)&As[k][ty * 8];
            *(float4*)&a[4] = *(float4*)&As[k][ty * 8 + 4];
            *(float4*)&b[0] = *(float4*)&Bs[k][tx * 4];
            #pragma unroll
            for (int i = 0; i < 8; i++)
                #pragma unroll
                for (int j = 0; j < 4; j++)
                    acc[i][j] += a[i] * b[j];
        }
        __syncthreads();
    }

    // ---- epilogue: scale by dinv[row], pack to fp16
    #pragma unroll
    for (int i = 0; i < 8; i++) {
        int gm = m0 + ty * 8 + i;
        if (gm < N_NODES) {
            float dv = g_dinv[gm];
            __half2* dst = &g_hh[gm * (D / 2) + (n0 + tx * 4) / 2];
            dst[0] = __floats2half2_rn(acc[i][0] * dv, acc[i][1] * dv);
            dst[1] = __floats2half2_rn(acc[i][2] * dv, acc[i][3] * dv);
        }
    }
}

// ---------------------------------------------------------------------------
// out[i,:] = dinv[i] * ( sum_{j: bit(i,j)} h[j,:] + h[i,:] )
// h already prescaled by dinv[j]; fp16 storage halves L2 traffic.
// 128 threads per row; thread t owns dims (2t, 2t+1) via __half2.
__global__ void agg_kernel(float* __restrict__ out) {
    __shared__ int s_idx[BUF];
    __shared__ int s_pc[CHUNK_WORDS + 1];
    int row = blockIdx.x;
    int t = threadIdx.x;
    const uint32_t* wrow = &g_bits[row * WPR];
    float2 acc = make_float2(0.0f, 0.0f);

    for (int w0 = 0; w0 < WPR; w0 += CHUNK_WORDS) {
        uint32_t myw = 0;
        if (t < CHUNK_WORDS) {
            int wi = w0 + t;
            myw = (wi < WPR) ? wrow[wi] : 0u;
            s_pc[t] = __popc(myw);
        }
        __syncthreads();
        if (t < CHUNK_WORDS) {
            int pos = 0, tot = 0;
            #pragma unroll 8
            for (int q = 0; q < CHUNK_WORDS; q++) {
                int p = s_pc[q];
                if (q < t) pos += p;
                tot += p;
            }
            uint32_t w = myw;
            int base = (w0 + t) * 32;
            while (w) {
                int b = __ffs(w) - 1;
                w &= w - 1;
                s_idx[pos++] = base + b;
            }
            if (t == 0) s_pc[CHUNK_WORDS] = tot;
        }
        __syncthreads();
        int cnt = s_pc[CHUNK_WORDS];
        #pragma unroll 4
        for (int k = 0; k < cnt; k++) {
            float2 f = __half22float2(g_hh[s_idx[k] * (D / 2) + t]);
            acc.x += f.x;
            acc.y += f.y;
        }
        __syncthreads();
    }
    float di = g_dinv[row];
    float2 self = __half22float2(g_hh[row * (D / 2) + t]);
    float2 o;
    o.x = di * (acc.x + self.x);
    o.y = di * (acc.y + self.y);
    ((float2*)out)[row * (D / 2) + t] = o;
}

// ---------------------------------------------------------------------------
extern "C" void kernel_launch(void* const* d_in, const int* in_sizes, int n_in,
                              void* d_out, int out_size) {
    const float* x  = (const float*)d_in[0];
    const int*   ei = (const int*)d_in[1];
    const float* w  = (const float*)d_in[2];
    float* out = (float*)d_out;

    void* bits_ptr = nullptr;
    void* odd_ptr = nullptr;
    cudaGetSymbolAddress(&bits_ptr, g_bits);
    cudaGetSymbolAddress(&odd_ptr, g_odd);
    cudaMemsetAsync(bits_ptr, 0, sizeof(uint32_t) * (size_t)N_NODES * WPR);
    cudaMemsetAsync(odd_ptr, 0, sizeof(int));

    detect_kernel<<<256, 256>>>(ei);
    set_bits_kernel<<<(E_EDGES + 255) / 256, 256>>>(ei);
    deg_kernel<<<(N_NODES + 7) / 8, 256>>>();
    gemm_kernel<<<dim3((N_NODES + BM - 1) / BM, D / BN), 128>>>(x, w);
    agg_kernel<<<N_NODES, 128>>>(out);
}

// round 3
// speedup vs baseline: 2.5299x; 1.7177x over previous
#include <cuda_runtime.h>
#include <cuda_fp16.h>
#include <cstdint>

#define N_NODES 10000
#define M_PAD   10048            // 157 * 64
#define WPR     313              // ceil(10000/32)
#define D       256
#define E_EDGES 320000
#define MAXDEG  1024             // >> max row degree (~110 for this graph)

// Scratch (no allocs allowed)
__device__ uint32_t g_bits[N_NODES * WPR];   // 12.52 MB bitmask
__device__ float    g_dinv[N_NODES];
__device__ __half2  g_hh[N_NODES * (D / 2)]; // h * dinv[row], fp16
__device__ __half   g_xh[M_PAD * D];         // x in fp16 (padded rows zero)
__device__ __half   g_wt[D * D];             // W^T in fp16 (n-major, k contiguous)
__device__ int      g_odd;                   // nonzero => edge_index is int32

// ---------------------------------------------------------------------------
// Detect edge_index dtype: if int64, every odd 32-bit word is zero.
__global__ void detect_kernel(const int* __restrict__ ei) {
    unsigned v = 0;
    int stride = 2 * gridDim.x * blockDim.x;
    for (int i = 2 * (blockIdx.x * blockDim.x + threadIdx.x) + 1; i < 2 * E_EDGES; i += stride)
        v |= (unsigned)ei[i];
    #pragma unroll
    for (int o = 16; o; o >>= 1) v |= __shfl_xor_sync(0xffffffffu, v, o);
    if ((threadIdx.x & 31) == 0 && v) atomicOr(&g_odd, 1);
}

// ---------------------------------------------------------------------------
// Set adjacency bits (symmetric, OR = idempotent dedup, order-independent)
__global__ void set_bits_kernel(const int* __restrict__ ei32) {
    int e = blockIdx.x * blockDim.x + threadIdx.x;
    if (e >= E_EDGES) return;
    int src, dst;
    if (g_odd == 0) {  // int64 layout
        const long long* ei = (const long long*)ei32;
        src = (int)ei[e];
        dst = (int)ei[E_EDGES + e];
    } else {
        src = ei32[e];
        dst = ei32[E_EDGES + e];
    }
    atomicOr(&g_bits[src * WPR + (dst >> 5)], 1u << (dst & 31));
    atomicOr(&g_bits[dst * WPR + (src >> 5)], 1u << (src & 31));
}

// ---------------------------------------------------------------------------
// dinv[i] = rsqrt(popcount(row i) + 1)
__global__ void deg_kernel() {
    int row = blockIdx.x * 8 + (threadIdx.x >> 5);
    if (row >= N_NODES) return;
    int lane = threadIdx.x & 31;
    const uint32_t* w = &g_bits[row * WPR];
    unsigned cnt = 0;
    for (int i = lane; i < WPR; i += 32) cnt += __popc(w[i]);
    #pragma unroll
    for (int o = 16; o; o >>= 1) cnt += __shfl_down_sync(0xffffffffu, cnt, o);
    if (lane == 0) g_dinv[row] = rsqrtf((float)cnt + 1.0f);
}

// ---------------------------------------------------------------------------
// Convert x -> fp16 (zero-pad rows), W -> W^T fp16
__global__ void convert_kernel(const float* __restrict__ x, const float* __restrict__ w) {
    int idx = blockIdx.x * blockDim.x + threadIdx.x;
    if (idx < M_PAD * D) {
        int row = idx >> 8;
        g_xh[idx] = (row < N_NODES) ? __float2half(x[idx]) : __half(0);
    }
    if (idx < D * D) {
        int k = idx >> 8, n = idx & 255;
        g_wt[n * D + k] = __float2half(w[idx]);   // coalesced read, scattered 2B write (128KB total)
    }
}

// ---------------------------------------------------------------------------
// Tensor-core GEMM: h = (x @ W) * dinv[row] -> fp16
// Block 64x64, 128 threads (4 warps 2x2), warp tile 32x32, mma m16n8k16.
#define GBK 64
#define LDP (GBK + 8)   // padded row length in halfs -> 144B row stride, LDSM conflict-free

__device__ __forceinline__ void ldsm4(uint32_t* r, uint32_t addr) {
    asm volatile("ldmatrix.sync.aligned.m8n8.x4.shared.b16 {%0,%1,%2,%3}, [%4];"
                 : "=r"(r[0]), "=r"(r[1]), "=r"(r[2]), "=r"(r[3]) : "r"(addr));
}
__device__ __forceinline__ void mma16816(float* c, const uint32_t* a, uint32_t b0, uint32_t b1) {
    asm volatile("mma.sync.aligned.m16n8k16.row.col.f32.f16.f16.f32 "
                 "{%0,%1,%2,%3},{%4,%5,%6,%7},{%8,%9},{%0,%1,%2,%3};"
                 : "+f"(c[0]), "+f"(c[1]), "+f"(c[2]), "+f"(c[3])
                 : "r"(a[0]), "r"(a[1]), "r"(a[2]), "r"(a[3]), "r"(b0), "r"(b1));
}

__global__ __launch_bounds__(128) void gemm_mma_kernel() {
    __shared__ __half xs[64][LDP];
    __shared__ __half ws[64][LDP];
    const int t = threadIdx.x;
    const int lane = t & 31, wid = t >> 5;
    const int warpm = wid >> 1, warpn = wid & 1;
    const int m0 = blockIdx.x * 64, n0 = blockIdx.y * 64;

    float acc[2][4][4];
    #pragma unroll
    for (int i = 0; i < 2; i++)
        #pragma unroll
        for (int j = 0; j < 4; j++)
            #pragma unroll
            for (int q = 0; q < 4; q++) acc[i][j][q] = 0.0f;

    const uint32_t xs_u = (uint32_t)__cvta_generic_to_shared(&xs[0][0]);
    const uint32_t ws_u = (uint32_t)__cvta_generic_to_shared(&ws[0][0]);
    const int lr = lane & 7, sel = lane >> 3;
    // A x4 tiles: (m+lr,k) (m+8+lr,k) (m+lr,k+8) (m+8+lr,k+8)
    const int a_row = warpm * 32 + lr + ((sel & 1) ? 8 : 0);
    const int a_col = (sel & 2) ? 8 : 0;
    const uint32_t aA = xs_u + (uint32_t)(a_row * LDP + a_col) * 2u;
    // B x4 tiles: (n+lr,k) (n+lr,k+8) (n+8+lr,k) (n+8+lr,k+8)
    const int b_row = warpn * 32 + lr + ((sel & 2) ? 8 : 0);
    const int b_col = (sel & 1) ? 8 : 0;
    const uint32_t aB = ws_u + (uint32_t)(b_row * LDP + b_col) * 2u;

    for (int k0 = 0; k0 < D; k0 += GBK) {
        #pragma unroll
        for (int j = 0; j < 4; j++) {
            int idx = t + 128 * j;
            int row = idx >> 3, c = (idx & 7) * 8;
            *(uint4*)&xs[row][c] = *(const uint4*)&g_xh[(m0 + row) * D + k0 + c];
            *(uint4*)&ws[row][c] = *(const uint4*)&g_wt[(n0 + row) * D + k0 + c];
        }
        __syncthreads();
        #pragma unroll
        for (int s = 0; s < GBK / 16; s++) {
            uint32_t A0[4], A1[4], B0[4], B1[4];
            ldsm4(A0, aA + s * 32u);
            ldsm4(A1, aA + 16u * LDP * 2u + s * 32u);
            ldsm4(B0, aB + s * 32u);
            ldsm4(B1, aB + 16u * LDP * 2u + s * 32u);
            mma16816(acc[0][0], A0, B0[0], B0[1]);
            mma16816(acc[0][1], A0, B0[2], B0[3]);
            mma16816(acc[0][2], A0, B1[0], B1[1]);
            mma16816(acc[0][3], A0, B1[2], B1[3]);
            mma16816(acc[1][0], A1, B0[0], B0[1]);
            mma16816(acc[1][1], A1, B0[2], B0[3]);
            mma16816(acc[1][2], A1, B1[0], B1[1]);
            mma16816(acc[1][3], A1, B1[2], B1[3]);
        }
        __syncthreads();
    }

    // epilogue: scale by dinv, pack fp16
    const int r_base = m0 + warpm * 32 + (lane >> 2);
    const int c_base = n0 + warpn * 32 + (lane & 3) * 2;
    #pragma unroll
    for (int mt = 0; mt < 2; mt++) {
        int gr0 = r_base + mt * 16;
        int gr1 = gr0 + 8;
        float dv0 = (gr0 < N_NODES) ? g_dinv[gr0] : 0.0f;
        float dv1 = (gr1 < N_NODES) ? g_dinv[gr1] : 0.0f;
        #pragma unroll
        for (int nt = 0; nt < 4; nt++) {
            int gc = c_base + nt * 8;
            if (gr0 < N_NODES)
                g_hh[gr0 * (D / 2) + (gc >> 1)] = __floats2half2_rn(acc[mt][nt][0] * dv0, acc[mt][nt][1] * dv0);
            if (gr1 < N_NODES)
                g_hh[gr1 * (D / 2) + (gc >> 1)] = __floats2half2_rn(acc[mt][nt][2] * dv1, acc[mt][nt][3] * dv1);
        }
    }
}

// ---------------------------------------------------------------------------
// out[i,:] = dinv[i] * ( sum_{j in N(i)} h[j,:] + h[i,:] )
// Single-pass extraction: thread t owns words [3t, 3t+3); block scan; 2 barriers.
__global__ void agg_kernel(float* __restrict__ out) {
    __shared__ int s_idx[MAXDEG];
    __shared__ int s_wsum[4];
    const int row = blockIdx.x;
    const int t = threadIdx.x;
    const int lane = t & 31, wid = t >> 5;
    const uint32_t* __restrict__ wr = &g_bits[row * WPR];

    uint32_t w[3];
    int cnt = 0;
    const int wbase = t * 3;
    #pragma unroll
    for (int i = 0; i < 3; i++) {
        int wi = wbase + i;
        w[i] = (wi < WPR) ? wr[wi] : 0u;
        cnt += __popc(w[i]);
    }
    // inclusive warp scan of cnt
    int inc = cnt;
    #pragma unroll
    for (int o = 1; o < 32; o <<= 1) {
        int v = __shfl_up_sync(0xffffffffu, inc, o);
        if (lane >= o) inc += v;
    }
    if (lane == 31) s_wsum[wid] = inc;
    __syncthreads();
    int base = 0, tot = 0;
    #pragma unroll
    for (int i = 0; i < 4; i++) {
        int v = s_wsum[i];
        if (i < wid) base += v;
        tot += v;
    }
    int pos = base + inc - cnt;   // exclusive prefix in word order
    #pragma unroll
    for (int i = 0; i < 3; i++) {
        uint32_t ww = w[i];
        int b32 = (wbase + i) * 32;
        while (ww) {
            int b = __ffs(ww) - 1;
            ww &= ww - 1;
            s_idx[pos++] = (b32 + b) * (D / 2);   // premultiplied row offset
        }
    }
    __syncthreads();

    const __half2* __restrict__ hh = g_hh;
    float2 acc = make_float2(0.0f, 0.0f);
    int k = 0;
    for (; k + 4 <= tot; k += 4) {
        __half2 h0 = hh[s_idx[k] + t];
        __half2 h1 = hh[s_idx[k + 1] + t];
        __half2 h2 = hh[s_idx[k + 2] + t];
        __half2 h3 = hh[s_idx[k + 3] + t];
        float2 f0 = __half22float2(h0), f1 = __half22float2(h1);
        float2 f2 = __half22float2(h2), f3 = __half22float2(h3);
        acc.x += f0.x + f1.x + f2.x + f3.x;
        acc.y += f0.y + f1.y + f2.y + f3.y;
    }
    for (; k < tot; k++) {
        float2 f = __half22float2(hh[s_idx[k] + t]);
        acc.x += f.x;
        acc.y += f.y;
    }
    float2 self = __half22float2(hh[row * (D / 2) + t]);
    float di = g_dinv[row];
    float2 o;
    o.x = di * (acc.x + self.x);
    o.y = di * (acc.y + self.y);
    ((float2*)out)[row * (D / 2) + t] = o;
}

// ---------------------------------------------------------------------------
extern "C" void kernel_launch(void* const* d_in, const int* in_sizes, int n_in,
                              void* d_out, int out_size) {
    const float* x  = (const float*)d_in[0];
    const int*   ei = (const int*)d_in[1];
    const float* w  = (const float*)d_in[2];
    float* out = (float*)d_out;

    void* bits_ptr = nullptr;
    void* odd_ptr = nullptr;
    cudaGetSymbolAddress(&bits_ptr, g_bits);
    cudaGetSymbolAddress(&odd_ptr, g_odd);
    cudaMemsetAsync(bits_ptr, 0, sizeof(uint32_t) * (size_t)N_NODES * WPR);
    cudaMemsetAsync(odd_ptr, 0, sizeof(int));

    detect_kernel<<<256, 256>>>(ei);
    set_bits_kernel<<<(E_EDGES + 255) / 256, 256>>>(ei);
    deg_kernel<<<(N_NODES + 7) / 8, 256>>>();
    convert_kernel<<<(M_PAD * D + 255) / 256, 256>>>(x, w);
    gemm_mma_kernel<<<dim3(M_PAD / 64, D / 64), 128>>>();
    agg_kernel<<<N_NODES, 128>>>(out);
}